// round 1
// baseline (speedup 1.0000x reference)
#include <cuda_runtime.h>
#include <cstdint>
#include <math.h>

// ---------------- problem constants ----------------
#define TOK      8192          // B*S tokens
#define HID      2048
#define FFN      7168
#define NE       8
#define NPAIR    (TOK * 2)     // top-2 -> exactly 16384 (token, expert) pairs
#define OUT_ELEMS ((size_t)TOK * HID)
#define MAXT     264           // max 64-row m-tiles across experts: 16384/64 + 8

// ---------------- device scratch (no allocations allowed) ----------------
__device__ int   g_cnt[NE];
__device__ int   g_off[NE];
__device__ int   g_cur[NE];
__device__ int   g_ntiles;
__device__ int   g_tile_e[MAXT];
__device__ int   g_tile_m[MAXT];
__device__ int   g_sel[NPAIR];
__device__ float g_selw[NPAIR];
__device__ int   g_ptok[NPAIR];
__device__ float g_pw[NPAIR];
__device__ int   g_pe[NPAIR];
__device__ float g_logit_dump[TOK * NE];                 // fallback if out buffer lacks logits
__device__ float g_xg[(size_t)NPAIR * HID];              // gathered scaled activations (134 MB)
__device__ float g_hmid[(size_t)NPAIR * FFN];            // silu(x w1^T)*(x w3^T)*w_r (470 MB)

// ---------------- helpers ----------------
__device__ __forceinline__ float to_tf32(float x) {
    unsigned u;
    asm("cvt.rna.tf32.f32 %0, %1;" : "=r"(u) : "f"(x));
    return __uint_as_float(u);
}

__device__ __forceinline__ void mma_tf32(float c[4], const unsigned a[4], const unsigned b[2]) {
    asm volatile(
        "mma.sync.aligned.m16n8k8.row.col.f32.tf32.tf32.f32 "
        "{%0,%1,%2,%3}, {%4,%5,%6,%7}, {%8,%9}, {%0,%1,%2,%3};\n"
        : "+f"(c[0]), "+f"(c[1]), "+f"(c[2]), "+f"(c[3])
        : "r"(a[0]), "r"(a[1]), "r"(a[2]), "r"(a[3]), "r"(b[0]), "r"(b[1]));
}

// ---------------- kernel 0: zero output + counters ----------------
__global__ void init_kernel(float4* out4) {
    size_t i      = (size_t)blockIdx.x * blockDim.x + threadIdx.x;
    size_t stride = (size_t)gridDim.x * blockDim.x;
    const size_t n4 = OUT_ELEMS / 4;
    float4 z = make_float4(0.f, 0.f, 0.f, 0.f);
    for (size_t j = i; j < n4; j += stride) out4[j] = z;
    if (blockIdx.x == 0 && threadIdx.x < NE) g_cnt[threadIdx.x] = 0;
}

// ---------------- kernel 1: router (logits, top-2, counts) ----------------
__global__ void router_kernel(const float* __restrict__ x,
                              const float* __restrict__ gate,
                              float* __restrict__ logits_out,
                              int write_logits) {
    int warp = threadIdx.x >> 5;
    int lane = threadIdx.x & 31;
    int tbase = blockIdx.x * 64 + warp * 8;

    for (int i = 0; i < 8; i++) {
        int t = tbase + i;
        const float4* xp = (const float4*)(x + (size_t)t * HID);
        float acc[NE];
#pragma unroll
        for (int e = 0; e < NE; e++) acc[e] = 0.f;

        for (int c = lane; c < HID / 4; c += 32) {
            float4 xv = __ldg(xp + c);
#pragma unroll
            for (int e = 0; e < NE; e++) {
                float4 gv = __ldg((const float4*)(gate + (size_t)e * HID) + c);
                acc[e] += xv.x * gv.x + xv.y * gv.y + xv.z * gv.z + xv.w * gv.w;
            }
        }
#pragma unroll
        for (int e = 0; e < NE; e++)
            for (int o = 16; o; o >>= 1) acc[e] += __shfl_xor_sync(0xffffffffu, acc[e], o);

        if (lane == 0) {
            float* lo = write_logits ? logits_out : g_logit_dump;
#pragma unroll
            for (int e = 0; e < NE; e++) lo[(size_t)t * NE + e] = acc[e];

            int e0 = 0;
            for (int e = 1; e < NE; e++) if (acc[e] > acc[e0]) e0 = e;
            int e1 = -1;
            for (int e = 0; e < NE; e++) {
                if (e == e0) continue;
                if (e1 < 0 || acc[e] > acc[e1]) e1 = e;
            }
            // normalized top-2 softmax weights: Z cancels
            float w0 = 1.f / (1.f + expf(acc[e1] - acc[e0]));
            float w1 = 1.f - w0;
            g_sel[t * 2 + 0] = e0; g_selw[t * 2 + 0] = w0;
            g_sel[t * 2 + 1] = e1; g_selw[t * 2 + 1] = w1;
            atomicAdd(&g_cnt[e0], 1);
            atomicAdd(&g_cnt[e1], 1);
        }
    }
}

// ---------------- kernel 2: scan + tile list ----------------
__global__ void scan_kernel() {
    if (threadIdx.x == 0) {
        int o = 0, nt = 0;
        for (int e = 0; e < NE; e++) {
            g_off[e] = o;
            g_cur[e] = o;
            int c = g_cnt[e];
            int tl = (c + 63) >> 6;
            for (int m = 0; m < tl; m++) { g_tile_e[nt] = e; g_tile_m[nt] = m; nt++; }
            o += c;
        }
        g_ntiles = nt;
    }
}

// ---------------- kernel 3: scatter pairs into per-expert segments ----------------
__global__ void scatter_kernel() {
    int t = blockIdx.x * blockDim.x + threadIdx.x;
    if (t >= TOK) return;
#pragma unroll
    for (int k = 0; k < 2; k++) {
        int e = g_sel[t * 2 + k];
        int pos = atomicAdd(&g_cur[e], 1);
        g_ptok[pos] = t;
        g_pw[pos]   = g_selw[t * 2 + k];
        g_pe[pos]   = e;
    }
}

// ---------------- kernel 4: gather + per-expert scale divide ----------------
__global__ void gather_kernel(const float* __restrict__ x,
                              const float* __restrict__ scales) {
    int r = blockIdx.x;
    int tok = g_ptok[r];
    int e   = g_pe[r];
    const float4* xp = (const float4*)(x + (size_t)tok * HID);
    const float4* sp = (const float4*)(scales + (size_t)e * HID);
    float4* dp = (float4*)(g_xg + (size_t)r * HID);
    for (int c = threadIdx.x; c < HID / 4; c += blockDim.x) {
        float4 xv = xp[c], sv = sp[c];
        float4 o;
        o.x = xv.x / sv.x; o.y = xv.y / sv.y; o.z = xv.z / sv.z; o.w = xv.w / sv.w;
        dp[c] = o;
    }
}

// ---------------- GEMM tiling config ----------------
#define BK  16
#define PAD 20   // 80B row pitch: 16B-aligned for float4 STS, conflict-free frag LDS

// ---------------- kernel 5: fused GEMM-1 (w1 & w3) + SiLU + routing weight ----------------
__global__ __launch_bounds__(256) void gemm1_kernel(const float* __restrict__ w1,
                                                    const float* __restrict__ w3) {
    int ti = blockIdx.y;
    if (ti >= g_ntiles) return;
    int e   = g_tile_e[ti];
    int mt  = g_tile_m[ti];
    int cnt = g_cnt[e];
    int off = g_off[e];
    int row0  = off + mt * 64;
    int mrows = cnt - mt * 64; if (mrows > 64) mrows = 64;
    int n0 = blockIdx.x * 64;

    __shared__ float As[64][PAD];
    __shared__ float B1s[64][PAD];
    __shared__ float B3s[64][PAD];

    int tid = threadIdx.x;
    int ldr = tid >> 2;        // 0..63
    int ldc = (tid & 3) * 4;   // 0,4,8,12

    const float* w1p = w1 + ((size_t)e * FFN + n0) * HID;
    const float* w3p = w3 + ((size_t)e * FFN + n0) * HID;

    int wid = tid >> 5, lane = tid & 31;
    int wm = (wid >> 2) * 32;  // 0 / 32
    int wn = (wid & 3) * 16;   // 0/16/32/48
    int lr = lane >> 2, lc = lane & 3;

    float c1[2][2][4], c2[2][2][4];
#pragma unroll
    for (int i = 0; i < 2; i++)
#pragma unroll
        for (int j = 0; j < 2; j++)
#pragma unroll
            for (int q = 0; q < 4; q++) { c1[i][j][q] = 0.f; c2[i][j][q] = 0.f; }

    for (int k0 = 0; k0 < HID; k0 += BK) {
        float4 av = make_float4(0.f, 0.f, 0.f, 0.f);
        if (ldr < mrows)
            av = *(const float4*)(g_xg + (size_t)(row0 + ldr) * HID + k0 + ldc);
        As[ldr][ldc + 0] = to_tf32(av.x);
        As[ldr][ldc + 1] = to_tf32(av.y);
        As[ldr][ldc + 2] = to_tf32(av.z);
        As[ldr][ldc + 3] = to_tf32(av.w);

        float4 b1 = *(const float4*)(w1p + (size_t)ldr * HID + k0 + ldc);
        B1s[ldr][ldc + 0] = to_tf32(b1.x);
        B1s[ldr][ldc + 1] = to_tf32(b1.y);
        B1s[ldr][ldc + 2] = to_tf32(b1.z);
        B1s[ldr][ldc + 3] = to_tf32(b1.w);

        float4 b3 = *(const float4*)(w3p + (size_t)ldr * HID + k0 + ldc);
        B3s[ldr][ldc + 0] = to_tf32(b3.x);
        B3s[ldr][ldc + 1] = to_tf32(b3.y);
        B3s[ldr][ldc + 2] = to_tf32(b3.z);
        B3s[ldr][ldc + 3] = to_tf32(b3.w);

        __syncthreads();
#pragma unroll
        for (int kk = 0; kk < BK; kk += 8) {
            unsigned a[2][4], bb1[2][2], bb3[2][2];
#pragma unroll
            for (int sm = 0; sm < 2; sm++) {
                int ar = wm + sm * 16 + lr;
                a[sm][0] = __float_as_uint(As[ar][kk + lc]);
                a[sm][1] = __float_as_uint(As[ar + 8][kk + lc]);
                a[sm][2] = __float_as_uint(As[ar][kk + 4 + lc]);
                a[sm][3] = __float_as_uint(As[ar + 8][kk + 4 + lc]);
            }
#pragma unroll
            for (int sn = 0; sn < 2; sn++) {
                int br = wn + sn * 8 + lr;
                bb1[sn][0] = __float_as_uint(B1s[br][kk + lc]);
                bb1[sn][1] = __float_as_uint(B1s[br][kk + 4 + lc]);
                bb3[sn][0] = __float_as_uint(B3s[br][kk + lc]);
                bb3[sn][1] = __float_as_uint(B3s[br][kk + 4 + lc]);
            }
#pragma unroll
            for (int sm = 0; sm < 2; sm++)
#pragma unroll
                for (int sn = 0; sn < 2; sn++) {
                    mma_tf32(c1[sm][sn], a[sm], bb1[sn]);
                    mma_tf32(c2[sm][sn], a[sm], bb3[sn]);
                }
        }
        __syncthreads();
    }

    // epilogue: hmid = silu(c1) * c2 * routing_weight
#pragma unroll
    for (int sm = 0; sm < 2; sm++) {
        int rbase = wm + sm * 16 + lr;
#pragma unroll
        for (int half = 0; half < 2; half++) {
            int r = rbase + half * 8;
            if (r < mrows) {
                float wr = g_pw[row0 + r];
                float* hp = g_hmid + (size_t)(row0 + r) * FFN + n0;
#pragma unroll
                for (int sn = 0; sn < 2; sn++) {
                    int col = wn + sn * 8 + lc * 2;
                    float v1a = c1[sm][sn][half * 2 + 0], v3a = c2[sm][sn][half * 2 + 0];
                    float v1b = c1[sm][sn][half * 2 + 1], v3b = c2[sm][sn][half * 2 + 1];
                    hp[col + 0] = (v1a / (1.f + expf(-v1a))) * v3a * wr;
                    hp[col + 1] = (v1b / (1.f + expf(-v1b))) * v3b * wr;
                }
            }
        }
    }
}

// ---------------- kernel 6: GEMM-2 (hmid @ w2^T) + scatter-add ----------------
__global__ __launch_bounds__(256) void gemm2_kernel(const float* __restrict__ w2,
                                                    float* __restrict__ out) {
    int ti = blockIdx.y;
    if (ti >= g_ntiles) return;
    int e   = g_tile_e[ti];
    int mt  = g_tile_m[ti];
    int cnt = g_cnt[e];
    int off = g_off[e];
    int row0  = off + mt * 64;
    int mrows = cnt - mt * 64; if (mrows > 64) mrows = 64;
    int n0 = blockIdx.x * 64;   // over HID

    __shared__ float As[64][PAD];
    __shared__ float Bs[64][PAD];

    int tid = threadIdx.x;
    int ldr = tid >> 2;
    int ldc = (tid & 3) * 4;

    const float* w2p = w2 + ((size_t)e * HID + n0) * FFN;

    int wid = tid >> 5, lane = tid & 31;
    int wm = (wid >> 2) * 32;
    int wn = (wid & 3) * 16;
    int lr = lane >> 2, lc = lane & 3;

    float cc[2][2][4];
#pragma unroll
    for (int i = 0; i < 2; i++)
#pragma unroll
        for (int j = 0; j < 2; j++)
#pragma unroll
            for (int q = 0; q < 4; q++) cc[i][j][q] = 0.f;

    for (int k0 = 0; k0 < FFN; k0 += BK) {
        float4 av = make_float4(0.f, 0.f, 0.f, 0.f);
        if (ldr < mrows)
            av = *(const float4*)(g_hmid + (size_t)(row0 + ldr) * FFN + k0 + ldc);
        As[ldr][ldc + 0] = to_tf32(av.x);
        As[ldr][ldc + 1] = to_tf32(av.y);
        As[ldr][ldc + 2] = to_tf32(av.z);
        As[ldr][ldc + 3] = to_tf32(av.w);

        float4 bv = *(const float4*)(w2p + (size_t)ldr * FFN + k0 + ldc);
        Bs[ldr][ldc + 0] = to_tf32(bv.x);
        Bs[ldr][ldc + 1] = to_tf32(bv.y);
        Bs[ldr][ldc + 2] = to_tf32(bv.z);
        Bs[ldr][ldc + 3] = to_tf32(bv.w);

        __syncthreads();
#pragma unroll
        for (int kk = 0; kk < BK; kk += 8) {
            unsigned a[2][4], bb[2][2];
#pragma unroll
            for (int sm = 0; sm < 2; sm++) {
                int ar = wm + sm * 16 + lr;
                a[sm][0] = __float_as_uint(As[ar][kk + lc]);
                a[sm][1] = __float_as_uint(As[ar + 8][kk + lc]);
                a[sm][2] = __float_as_uint(As[ar][kk + 4 + lc]);
                a[sm][3] = __float_as_uint(As[ar + 8][kk + 4 + lc]);
            }
#pragma unroll
            for (int sn = 0; sn < 2; sn++) {
                int br = wn + sn * 8 + lr;
                bb[sn][0] = __float_as_uint(Bs[br][kk + lc]);
                bb[sn][1] = __float_as_uint(Bs[br][kk + 4 + lc]);
            }
#pragma unroll
            for (int sm = 0; sm < 2; sm++)
#pragma unroll
                for (int sn = 0; sn < 2; sn++)
                    mma_tf32(cc[sm][sn], a[sm], bb[sn]);
        }
        __syncthreads();
    }

    // epilogue: atomic scatter-add into out[token][h]
#pragma unroll
    for (int sm = 0; sm < 2; sm++) {
        int rbase = wm + sm * 16 + lr;
#pragma unroll
        for (int half = 0; half < 2; half++) {
            int r = rbase + half * 8;
            if (r < mrows) {
                int tok = g_ptok[row0 + r];
                float* op = out + (size_t)tok * HID + n0;
#pragma unroll
                for (int sn = 0; sn < 2; sn++) {
                    int col = wn + sn * 8 + lc * 2;
                    atomicAdd(&op[col + 0], cc[sm][sn][half * 2 + 0]);
                    atomicAdd(&op[col + 1], cc[sm][sn][half * 2 + 1]);
                }
            }
        }
    }
}

// ---------------- host launch ----------------
extern "C" void kernel_launch(void* const* d_in, const int* in_sizes, int n_in,
                              void* d_out, int out_size) {
    const float* x      = (const float*)d_in[0]; // hidden_states [B,S,H]
    const float* gate   = (const float*)d_in[1]; // gate_w [E,H]
    const float* w1     = (const float*)d_in[2]; // [E,F,H]
    const float* w3     = (const float*)d_in[3]; // [E,F,H]
    const float* w2     = (const float*)d_in[4]; // [E,H,F]
    const float* scales = (const float*)d_in[5]; // [E,H]

    float* out = (float*)d_out;
    int write_logits = ((size_t)out_size >= OUT_ELEMS + (size_t)TOK * NE) ? 1 : 0;
    float* logits = out + OUT_ELEMS;

    init_kernel<<<2048, 256>>>((float4*)out);
    router_kernel<<<TOK / 64, 256>>>(x, gate, logits, write_logits);
    scan_kernel<<<1, 32>>>();
    scatter_kernel<<<TOK / 256, 256>>>();
    gather_kernel<<<NPAIR, 128>>>(x, scales);

    dim3 g1(FFN / 64, MAXT);
    gemm1_kernel<<<g1, 256>>>(w1, w3);

    dim3 g2(HID / 64, MAXT);
    gemm2_kernel<<<g2, 256>>>(w2, out);
}